// round 15
// baseline (speedup 1.0000x reference)
#include <cuda_runtime.h>
#include <cuda_fp16.h>
#include <math.h>

#define TOK 1024
#define HDIM 2880
#define DDIM 2880
#define NEXP 8
#define GUCOLS 5760
#define ALPHA 1.702f
#define LIMIT 7.0f

__device__ __align__(16) __half g_wgu_h[(size_t)NEXP*HDIM*GUCOLS];
__device__ __align__(16) __half g_wd_h [(size_t)NEXP*DDIM*HDIM];
__device__ __align__(16) __half g_x_h  [(size_t)TOK*HDIM];
__device__ __align__(16) __half g_a_h  [(size_t)NEXP*TOK*DDIM];

__device__ __forceinline__ unsigned su32(const void* p){
    unsigned a; asm("{ .reg .u64 t; cvta.to.shared.u64 t, %1; cvt.u32.u64 %0, t; }":"=r"(a):"l"(p)); return a;
}
template<int N> __device__ __forceinline__ void cpwait(){
    asm volatile("cp.async.wait_group %0;"::"n"(N):"memory");
}
__device__ __forceinline__ void cpcommit(){
    asm volatile("cp.async.commit_group;":::"memory");
}
__device__ __forceinline__ void cpa16(unsigned d, const void* s){
    asm volatile("cp.async.cg.shared.global [%0], [%1], 16;"::"r"(d),"l"(s):"memory");
}
__device__ __forceinline__ void ldsm4(unsigned* r, unsigned a){
    asm volatile("ldmatrix.sync.aligned.m8n8.x4.shared.b16 {%0,%1,%2,%3}, [%4];"
        :"=r"(r[0]),"=r"(r[1]),"=r"(r[2]),"=r"(r[3]):"r"(a));
}
__device__ __forceinline__ void ldsm4t(unsigned* r, unsigned a){
    asm volatile("ldmatrix.sync.aligned.m8n8.x4.trans.shared.b16 {%0,%1,%2,%3}, [%4];"
        :"=r"(r[0]),"=r"(r[1]),"=r"(r[2]),"=r"(r[3]):"r"(a));
}
__device__ __forceinline__ void ldsm2t(unsigned* r, unsigned a){
    asm volatile("ldmatrix.sync.aligned.m8n8.x2.trans.shared.b16 {%0,%1}, [%2];"
        :"=r"(r[0]),"=r"(r[1]):"r"(a));
}
__device__ __forceinline__ void mma_fp(float* c, const unsigned* a, const unsigned* b){
    asm volatile("mma.sync.aligned.m16n8k16.row.col.f32.f16.f16.f32 "
        "{%0,%1,%2,%3},{%4,%5,%6,%7},{%8,%9},{%0,%1,%2,%3};"
        : "+f"(c[0]),"+f"(c[1]),"+f"(c[2]),"+f"(c[3])
        : "r"(a[0]),"r"(a[1]),"r"(a[2]),"r"(a[3]),"r"(b[0]),"r"(b[1]));
}
__device__ __forceinline__ uint2 cvt4(float4 f){
    uint2 v;
    v.x=(unsigned)__half_as_ushort(__float2half_rn(f.x))
       |((unsigned)__half_as_ushort(__float2half_rn(f.y))<<16);
    v.y=(unsigned)__half_as_ushort(__float2half_rn(f.z))
       |((unsigned)__half_as_ushort(__float2half_rn(f.w))<<16);
    return v;
}

// -------- fp32 -> fp16 convert of x + wgu (wd handled inside gemm1) --------
#define CVT_N1 ((long long)TOK*HDIM/4)
#define CVT_N2 ((long long)NEXP*HDIM*GUCOLS/4)

__global__ void cvt_kernel(const float4* __restrict__ x, const float4* __restrict__ wgu){
    const long long NT=CVT_N1+CVT_N2;
    long long i=(long long)blockIdx.x*blockDim.x+threadIdx.x, st=(long long)gridDim.x*blockDim.x;
    for(; i<NT; i+=st){
        const float4* s; uint2* d; long long j;
        if(i<CVT_N1){ s=x; d=(uint2*)g_x_h; j=i; }
        else { s=wgu; d=(uint2*)g_wgu_h; j=i-CVT_N1; }
        d[j]=cvt4(s[j]);
    }
}

// ======================= GEMM1: gate_up + SwiGLU (+ hidden wd convert) ==========
// CTA tile: 128 x 128. 128 thr, 4 warps (2m x 2n of 64x64). 4 stages.
// Each thread converts one wd float4 per iter (kc<45), pipelined LDG->STG.
#define S1_STAGE 16384

__global__ __launch_bounds__(128,2)
void gemm1_kernel(const float* __restrict__ rw, const float* __restrict__ bgu,
                  const float4* __restrict__ wd4)
{
    extern __shared__ __align__(16) char dsm[];
    __shared__ float sBias[128];
    __shared__ float sRw[128];
    const int tid=threadIdx.x, lane=tid&31, w=tid>>5;
    const int e=blockIdx.z, m0=blockIdx.y*128, c0=blockIdx.x*128, dbase=blockIdx.x*64;
    const unsigned db=su32(dsm);
    sBias[tid]=bgu[(size_t)e*GUCOLS+c0+tid];
    sRw[tid]=rw[(size_t)(m0+tid)*NEXP+e];

    const __half* xh = g_x_h + (size_t)m0*HDIM;
    const __half* wh = g_wgu_h + (size_t)e*HDIM*GUCOLS + c0;

    // wd-convert job base: idx(kc) = kc*368640 + cta*128 + tid  (45 iters covers all)
    const unsigned cta = (unsigned)blockIdx.z*360u + (unsigned)blockIdx.y*45u + (unsigned)blockIdx.x;
    const size_t wdb = (size_t)cta*128u + (unsigned)tid;
    uint2* wdo = (uint2*)g_wd_h;

    unsigned aoffv[4], boffv[4];
    unsigned asrc[4];
    unsigned bsrc_r[4], bsrc_c[4];
    #pragma unroll
    for(int i=0;i<4;i++){
        int li=tid+128*i;
        int ar=li>>2, ac=li&3;
        aoffv[i]=(unsigned)ar*64 + (unsigned)((ac ^ ((ar>>1)&3))*16);
        asrc[i]=(unsigned)ar*HDIM + ac*8;
        int br2=li>>4, bc2=li&15;
        boffv[i]=8192u + (unsigned)br2*256 + (unsigned)((bc2 ^ (br2&7))*16);
        bsrc_r[i]=(unsigned)br2; bsrc_c[i]=(unsigned)bc2*8;
    }

    const int NCH=HDIM/32; // 90
    auto LOAD=[&](int kc){
        if(kc<NCH){
            const unsigned st=db+(unsigned)(kc&3)*S1_STAGE;
            const int k0=kc*32;
            #pragma unroll
            for(int i=0;i<4;i++)
                cpa16(st+aoffv[i], xh+asrc[i]+k0);
            #pragma unroll
            for(int i=0;i<4;i++)
                cpa16(st+boffv[i], wh+(size_t)(k0+bsrc_r[i])*GUCOLS+bsrc_c[i]);
        }
        cpcommit();
    };

    const int mw=(w&1)*64, nw=(w>>1)*64;
    float C[4][8][4];
    #pragma unroll
    for(int i=0;i<4;i++)
        #pragma unroll
        for(int j=0;j<8;j++)
            #pragma unroll
            for(int q=0;q<4;q++) C[i][j][q]=0.f;

    const int rl=lane&15;
    const unsigned aswz=((rl>>1)&3);
    const unsigned bswz=(lane&7);

    float4 pend;
    LOAD(0); LOAD(1); LOAD(2);
    pend = wd4[wdb];                 // prefetch wd convert job for kc=0
    for(int kc=0;kc<NCH;kc++){
        if(kc==NCH-1) cpwait<0>(); else cpwait<2>();
        __syncthreads();
        LOAD(kc+3);
        // hidden wd conversion: store previous, prefetch next
        if(kc<45){
            uint2 v=cvt4(pend);
            wdo[(size_t)kc*368640u + wdb]=v;
            if(kc+1<45) pend = wd4[(size_t)(kc+1)*368640u + wdb];
        }
        const unsigned ab=db+(unsigned)(kc&3)*S1_STAGE;
        const unsigned bb=ab+8192;
        #pragma unroll
        for(int ks=0;ks<2;ks++){
            unsigned a[4][4],b_h[8][2];
            const unsigned boff=bb+(unsigned)(ks*16+rl)*256;
            #pragma unroll
            for(int p=0;p<4;p++){
                unsigned r4[4];
                ldsm4t(r4, boff+((((nw>>3)+2*p+(lane>>4))^bswz)*16));
                b_h[2*p][0]=r4[0];   b_h[2*p][1]=r4[1];
                b_h[2*p+1][0]=r4[2]; b_h[2*p+1][1]=r4[3];
            }
            const unsigned aoff=ab+(unsigned)(mw+rl)*64+((((lane>>4)+ks*2)^aswz)*16);
            #pragma unroll
            for(int mt=0;mt<4;mt++) ldsm4(a[mt],aoff+mt*1024);
            #pragma unroll
            for(int mt=0;mt<4;mt++)
                #pragma unroll
                for(int nt=0;nt<8;nt++)
                    mma_fp(C[mt][nt],a[mt],b_h[nt]);
        }
    }
    __syncthreads();

    float* sv=(float*)dsm;
    const int grp=lane>>2, tq=lane&3;
    #pragma unroll
    for(int mt=0;mt<4;mt++)
        #pragma unroll
        for(int nt=0;nt<8;nt++){
            const int colL=nw+nt*8+tq*2;
            const int d=(nw>>1)+nt*4+tq;
            #pragma unroll
            for(int h=0;h<2;h++){
                const int row=mw+mt*16+grp+h*8;
                float g=C[mt][nt][2*h]  +sBias[colL];
                float u=C[mt][nt][2*h+1]+sBias[colL+1];
                g=fminf(g,LIMIT);
                u=fminf(fmaxf(u,-LIMIT),LIMIT);
                float glu=g/(1.0f+__expf(-ALPHA*g));
                sv[row*68+d]=(u+1.0f)*glu*sRw[row];
            }
        }
    __syncthreads();
    {
        const int row=tid;
        __half* oh=g_a_h+((size_t)e*TOK+m0+row)*DDIM+dbase;
        #pragma unroll
        for(int j=0;j<64;j+=8){
            unsigned hv[4];
            #pragma unroll
            for(int q=0;q<4;q++){
                float aa=sv[row*68+j+2*q], b=sv[row*68+j+2*q+1];
                hv[q]=(unsigned)__half_as_ushort(__float2half_rn(aa))
                     |((unsigned)__half_as_ushort(__float2half_rn(b))<<16);
            }
            *(uint4*)(oh+j)=make_uint4(hv[0],hv[1],hv[2],hv[3]);
        }
    }
}

// ======================= GEMM2: down proj + bias + expert sum (R14 config) ========
#define S2_BHI 8192
#define S2_STAGE 13824

__global__ __launch_bounds__(128,2)
void gemm2_kernel(const float* __restrict__ rw, const float* __restrict__ bd,
                  float* __restrict__ out)
{
    extern __shared__ __align__(16) char dsm[];
    __shared__ float sRw[128*8];
    __shared__ float sBd[8*80];
    const int tid=threadIdx.x, lane=tid&31, w=tid>>5;
    const int m0=blockIdx.y*128, h0=blockIdx.x*80;
    const unsigned db=su32(dsm);
    for(int i=tid;i<1024;i+=128) sRw[i]=rw[(size_t)(m0+(i>>3))*NEXP+(i&7)];
    for(int i=tid;i<640;i+=128) sBd[i]=bd[(size_t)(i/80)*HDIM+h0+(i%80)];

    unsigned aoffv[4], asrc[4];
    #pragma unroll
    for(int i=0;i<4;i++){
        int li=tid+128*i;
        int ar=li>>2, ac=li&3;
        aoffv[i]=(unsigned)ar*64 + (unsigned)((ac ^ ((ar>>1)&3))*16);
        asrc[i]=(unsigned)ar*DDIM + ac*8;
    }

    const int NCH=NEXP*90; // 720
    auto LOAD=[&](int kc){
        if(kc<NCH){
            const int e=kc/90, kl=(kc-e*90)*32;
            const unsigned st=db+(unsigned)(kc&3)*S2_STAGE;
            const __half* ah=g_a_h+((size_t)e*TOK+m0)*DDIM+kl;
            #pragma unroll
            for(int i=0;i<4;i++)
                cpa16(st+aoffv[i], ah+asrc[i]);
            const __half* bh=g_wd_h+((size_t)e*DDIM+kl)*HDIM+h0;
            #pragma unroll
            for(int i=0;i<3;i++){
                int ch=tid+128*i;
                if(ch<320){
                    int r=ch/10, c=ch-r*10;
                    cpa16(st+S2_BHI+r*176+c*16, bh+(size_t)r*HDIM+c*8);
                }
            }
        }
        cpcommit();
    };

    const int mw=(w&1)*64, nw=(w>>1)*40;
    float C[4][5][4];
    #pragma unroll
    for(int i=0;i<4;i++)
        #pragma unroll
        for(int j=0;j<5;j++)
            #pragma unroll
            for(int q=0;q<4;q++) C[i][j][q]=0.f;

    const int rl=lane&15;
    const unsigned aswz=((rl>>1)&3);

    LOAD(0); LOAD(1); LOAD(2);
    for(int kc=0;kc<NCH;kc++){
        if(kc==NCH-1) cpwait<0>(); else cpwait<2>();
        __syncthreads();
        LOAD(kc+3);
        const unsigned ab=db+(unsigned)(kc&3)*S2_STAGE;
        #pragma unroll
        for(int ks=0;ks<2;ks++){
            unsigned a[4][4],b_h[5][2];
            const unsigned bbase=ab+S2_BHI+(unsigned)(ks*16+rl)*176;
            #pragma unroll
            for(int p=0;p<2;p++){
                unsigned r4[4];
                ldsm4t(r4, bbase+(unsigned)(nw+(2*p+(lane>>4))*8)*2);
                b_h[2*p][0]=r4[0];   b_h[2*p][1]=r4[1];
                b_h[2*p+1][0]=r4[2]; b_h[2*p+1][1]=r4[3];
            }
            ldsm2t(b_h[4],bbase+(unsigned)(nw+4*8)*2);
            const unsigned aoff=ab+(unsigned)(mw+rl)*64+((((lane>>4)+ks*2)^aswz)*16);
            #pragma unroll
            for(int mt=0;mt<4;mt++) ldsm4(a[mt],aoff+mt*1024);
            #pragma unroll
            for(int mt=0;mt<4;mt++)
                #pragma unroll
                for(int nt=0;nt<5;nt++)
                    mma_fp(C[mt][nt],a[mt],b_h[nt]);
        }
    }

    const int grp=lane>>2, tq=lane&3;
    #pragma unroll
    for(int nt=0;nt<5;nt++){
        const int colL=nw+nt*8+tq*2;
        const int col=h0+colL;
        #pragma unroll
        for(int mt=0;mt<4;mt++)
            #pragma unroll
            for(int h=0;h<2;h++){
                const int row=mw+mt*16+grp+h*8;
                float v0=C[mt][nt][2*h], v1=C[mt][nt][2*h+1];
                #pragma unroll
                for(int e2=0;e2<NEXP;e2++){
                    float r=sRw[row*8+e2];
                    v0=fmaf(r,sBd[e2*80+colL],v0);
                    v1=fmaf(r,sBd[e2*80+colL+1],v1);
                }
                float2 t; t.x=v0; t.y=v1;
                *(float2*)(out+(size_t)(m0+row)*HDIM+col)=t;
            }
    }
}

extern "C" void kernel_launch(void* const* d_in, const int* in_sizes, int n_in,
                              void* d_out, int out_size)
{
    const float* x  =(const float*)d_in[0];
    const float* rw =(const float*)d_in[1];
    const float* wgu=(const float*)d_in[2];
    const float* bgu=(const float*)d_in[3];
    const float* wd =(const float*)d_in[4];
    const float* bd =(const float*)d_in[5];
    float* out=(float*)d_out;

    cudaFuncSetAttribute(gemm1_kernel, cudaFuncAttributeMaxDynamicSharedMemorySize, 4*S1_STAGE);
    cudaFuncSetAttribute(gemm2_kernel, cudaFuncAttributeMaxDynamicSharedMemorySize, 4*S2_STAGE);

    cvt_kernel<<<2368,256>>>((const float4*)x,(const float4*)wgu);
    gemm1_kernel<<<dim3(45,8,NEXP),128,4*S1_STAGE>>>(rw,bgu,(const float4*)wd);
    gemm2_kernel<<<dim3(36,8),128,4*S2_STAGE>>>(rw,bd,out);
}

// round 16
// speedup vs baseline: 1.0075x; 1.0075x over previous
#include <cuda_runtime.h>
#include <cuda_fp16.h>
#include <math.h>

#define TOK 1024
#define HDIM 2880
#define DDIM 2880
#define NEXP 8
#define GUCOLS 5760
#define ALPHA 1.702f
#define LIMIT 7.0f

__device__ __align__(16) __half g_wgu_h[(size_t)NEXP*HDIM*GUCOLS];
__device__ __align__(16) __half g_wd_h [(size_t)NEXP*DDIM*HDIM];
__device__ __align__(16) __half g_x_h  [(size_t)TOK*HDIM];
__device__ __align__(16) __half g_a_h  [(size_t)NEXP*TOK*DDIM];

__device__ __forceinline__ unsigned su32(const void* p){
    unsigned a; asm("{ .reg .u64 t; cvta.to.shared.u64 t, %1; cvt.u32.u64 %0, t; }":"=r"(a):"l"(p)); return a;
}
template<int N> __device__ __forceinline__ void cpwait(){
    asm volatile("cp.async.wait_group %0;"::"n"(N):"memory");
}
__device__ __forceinline__ void cpcommit(){
    asm volatile("cp.async.commit_group;":::"memory");
}
__device__ __forceinline__ void cpa16(unsigned d, const void* s){
    asm volatile("cp.async.cg.shared.global [%0], [%1], 16;"::"r"(d),"l"(s):"memory");
}
__device__ __forceinline__ void ldsm4(unsigned* r, unsigned a){
    asm volatile("ldmatrix.sync.aligned.m8n8.x4.shared.b16 {%0,%1,%2,%3}, [%4];"
        :"=r"(r[0]),"=r"(r[1]),"=r"(r[2]),"=r"(r[3]):"r"(a));
}
__device__ __forceinline__ void ldsm4t(unsigned* r, unsigned a){
    asm volatile("ldmatrix.sync.aligned.m8n8.x4.trans.shared.b16 {%0,%1,%2,%3}, [%4];"
        :"=r"(r[0]),"=r"(r[1]),"=r"(r[2]),"=r"(r[3]):"r"(a));
}
__device__ __forceinline__ void ldsm2t(unsigned* r, unsigned a){
    asm volatile("ldmatrix.sync.aligned.m8n8.x2.trans.shared.b16 {%0,%1}, [%2];"
        :"=r"(r[0]),"=r"(r[1]):"r"(a));
}
__device__ __forceinline__ void mma_fp(float* c, const unsigned* a, const unsigned* b){
    asm volatile("mma.sync.aligned.m16n8k16.row.col.f32.f16.f16.f32 "
        "{%0,%1,%2,%3},{%4,%5,%6,%7},{%8,%9},{%0,%1,%2,%3};"
        : "+f"(c[0]),"+f"(c[1]),"+f"(c[2]),"+f"(c[3])
        : "r"(a[0]),"r"(a[1]),"r"(a[2]),"r"(a[3]),"r"(b[0]),"r"(b[1]));
}
__device__ __forceinline__ uint2 cvt4(float4 f){
    uint2 v;
    v.x=(unsigned)__half_as_ushort(__float2half_rn(f.x))
       |((unsigned)__half_as_ushort(__float2half_rn(f.y))<<16);
    v.y=(unsigned)__half_as_ushort(__float2half_rn(f.z))
       |((unsigned)__half_as_ushort(__float2half_rn(f.w))<<16);
    return v;
}

// -------- fused fp32 -> fp16 convert of x, wgu, wd (single launch) --------
#define CVT_N1 ((long long)TOK*HDIM/4)
#define CVT_N2 ((long long)NEXP*HDIM*GUCOLS/4)
#define CVT_N3 ((long long)NEXP*DDIM*HDIM/4)

__global__ void cvt_kernel(const float4* __restrict__ x, const float4* __restrict__ wgu,
                           const float4* __restrict__ wd){
    const long long NT=CVT_N1+CVT_N2+CVT_N3;
    long long i=(long long)blockIdx.x*blockDim.x+threadIdx.x, st=(long long)gridDim.x*blockDim.x;
    for(; i<NT; i+=st){
        const float4* s; uint2* d; long long j;
        if(i<CVT_N1){ s=x; d=(uint2*)g_x_h; j=i; }
        else if(i<CVT_N1+CVT_N2){ s=wgu; d=(uint2*)g_wgu_h; j=i-CVT_N1; }
        else { s=wd; d=(uint2*)g_wd_h; j=i-CVT_N1-CVT_N2; }
        d[j]=cvt4(s[j]);
    }
}

// ======================= GEMM1: gate_up + SwiGLU ==========
// CTA tile: 128 x 128. 128 thr, 4 warps (2m x 2n of 64x64). 4 stages.
// Fragment loads for both ks grouped before the MMA blocks (R11 pattern).
#define S1_STAGE 16384

__global__ __launch_bounds__(128,2)
void gemm1_kernel(const float* __restrict__ rw, const float* __restrict__ bgu)
{
    extern __shared__ __align__(16) char dsm[];
    __shared__ float sBias[128];
    __shared__ float sRw[128];
    const int tid=threadIdx.x, lane=tid&31, w=tid>>5;
    const int e=blockIdx.z, m0=blockIdx.y*128, c0=blockIdx.x*128, dbase=blockIdx.x*64;
    const unsigned db=su32(dsm);
    sBias[tid]=bgu[(size_t)e*GUCOLS+c0+tid];
    sRw[tid]=rw[(size_t)(m0+tid)*NEXP+e];

    const __half* xh = g_x_h + (size_t)m0*HDIM;
    const __half* wh = g_wgu_h + (size_t)e*HDIM*GUCOLS + c0;

    unsigned aoffv[4], boffv[4];
    unsigned asrc[4];
    unsigned bsrc_r[4], bsrc_c[4];
    #pragma unroll
    for(int i=0;i<4;i++){
        int li=tid+128*i;
        int ar=li>>2, ac=li&3;
        aoffv[i]=(unsigned)ar*64 + (unsigned)((ac ^ ((ar>>1)&3))*16);
        asrc[i]=(unsigned)ar*HDIM + ac*8;
        int br2=li>>4, bc2=li&15;
        boffv[i]=8192u + (unsigned)br2*256 + (unsigned)((bc2 ^ (br2&7))*16);
        bsrc_r[i]=(unsigned)br2; bsrc_c[i]=(unsigned)bc2*8;
    }

    const int NCH=HDIM/32; // 90
    auto LOAD=[&](int kc){
        if(kc<NCH){
            const unsigned st=db+(unsigned)(kc&3)*S1_STAGE;
            const int k0=kc*32;
            #pragma unroll
            for(int i=0;i<4;i++)
                cpa16(st+aoffv[i], xh+asrc[i]+k0);
            #pragma unroll
            for(int i=0;i<4;i++)
                cpa16(st+boffv[i], wh+(size_t)(k0+bsrc_r[i])*GUCOLS+bsrc_c[i]);
        }
        cpcommit();
    };

    const int mw=(w&1)*64, nw=(w>>1)*64;
    float C[4][8][4];
    #pragma unroll
    for(int i=0;i<4;i++)
        #pragma unroll
        for(int j=0;j<8;j++)
            #pragma unroll
            for(int q=0;q<4;q++) C[i][j][q]=0.f;

    const int rl=lane&15;
    const unsigned aswz=((rl>>1)&3);
    const unsigned bswz=(lane&7);

    LOAD(0); LOAD(1); LOAD(2);
    for(int kc=0;kc<NCH;kc++){
        if(kc==NCH-1) cpwait<0>(); else cpwait<2>();
        __syncthreads();
        LOAD(kc+3);
        const unsigned ab=db+(unsigned)(kc&3)*S1_STAGE;
        const unsigned bb=ab+8192;
        // group fragment loads for both ks before the MMA blocks
        unsigned a[2][4][4], b_h[2][8][2];
        #pragma unroll
        for(int ks=0;ks<2;ks++){
            const unsigned boff=bb+(unsigned)(ks*16+rl)*256;
            #pragma unroll
            for(int p=0;p<4;p++){
                unsigned r4[4];
                ldsm4t(r4, boff+((((nw>>3)+2*p+(lane>>4))^bswz)*16));
                b_h[ks][2*p][0]=r4[0];   b_h[ks][2*p][1]=r4[1];
                b_h[ks][2*p+1][0]=r4[2]; b_h[ks][2*p+1][1]=r4[3];
            }
            const unsigned aoff=ab+(unsigned)(mw+rl)*64+((((lane>>4)+ks*2)^aswz)*16);
            #pragma unroll
            for(int mt=0;mt<4;mt++) ldsm4(a[ks][mt],aoff+mt*1024);
        }
        #pragma unroll
        for(int ks=0;ks<2;ks++)
            #pragma unroll
            for(int mt=0;mt<4;mt++)
                #pragma unroll
                for(int nt=0;nt<8;nt++)
                    mma_fp(C[mt][nt],a[ks][mt],b_h[ks][nt]);
    }
    __syncthreads();

    float* sv=(float*)dsm;
    const int grp=lane>>2, tq=lane&3;
    #pragma unroll
    for(int mt=0;mt<4;mt++)
        #pragma unroll
        for(int nt=0;nt<8;nt++){
            const int colL=nw+nt*8+tq*2;
            const int d=(nw>>1)+nt*4+tq;
            #pragma unroll
            for(int h=0;h<2;h++){
                const int row=mw+mt*16+grp+h*8;
                float g=C[mt][nt][2*h]  +sBias[colL];
                float u=C[mt][nt][2*h+1]+sBias[colL+1];
                g=fminf(g,LIMIT);
                u=fminf(fmaxf(u,-LIMIT),LIMIT);
                float glu=g/(1.0f+__expf(-ALPHA*g));
                sv[row*68+d]=(u+1.0f)*glu*sRw[row];
            }
        }
    __syncthreads();
    {
        const int row=tid;
        __half* oh=g_a_h+((size_t)e*TOK+m0+row)*DDIM+dbase;
        #pragma unroll
        for(int j=0;j<64;j+=8){
            unsigned hv[4];
            #pragma unroll
            for(int q=0;q<4;q++){
                float aa=sv[row*68+j+2*q], b=sv[row*68+j+2*q+1];
                hv[q]=(unsigned)__half_as_ushort(__float2half_rn(aa))
                     |((unsigned)__half_as_ushort(__float2half_rn(b))<<16);
            }
            *(uint4*)(oh+j)=make_uint4(hv[0],hv[1],hv[2],hv[3]);
        }
    }
}

// ======================= GEMM2: down proj + bias + expert sum (R14 config) ========
#define S2_BHI 8192
#define S2_STAGE 13824

__global__ __launch_bounds__(128,2)
void gemm2_kernel(const float* __restrict__ rw, const float* __restrict__ bd,
                  float* __restrict__ out)
{
    extern __shared__ __align__(16) char dsm[];
    __shared__ float sRw[128*8];
    __shared__ float sBd[8*80];
    const int tid=threadIdx.x, lane=tid&31, w=tid>>5;
    const int m0=blockIdx.y*128, h0=blockIdx.x*80;
    const unsigned db=su32(dsm);
    for(int i=tid;i<1024;i+=128) sRw[i]=rw[(size_t)(m0+(i>>3))*NEXP+(i&7)];
    for(int i=tid;i<640;i+=128) sBd[i]=bd[(size_t)(i/80)*HDIM+h0+(i%80)];

    unsigned aoffv[4], asrc[4];
    #pragma unroll
    for(int i=0;i<4;i++){
        int li=tid+128*i;
        int ar=li>>2, ac=li&3;
        aoffv[i]=(unsigned)ar*64 + (unsigned)((ac ^ ((ar>>1)&3))*16);
        asrc[i]=(unsigned)ar*DDIM + ac*8;
    }

    const int NCH=NEXP*90; // 720
    auto LOAD=[&](int kc){
        if(kc<NCH){
            const int e=kc/90, kl=(kc-e*90)*32;
            const unsigned st=db+(unsigned)(kc&3)*S2_STAGE;
            const __half* ah=g_a_h+((size_t)e*TOK+m0)*DDIM+kl;
            #pragma unroll
            for(int i=0;i<4;i++)
                cpa16(st+aoffv[i], ah+asrc[i]);
            const __half* bh=g_wd_h+((size_t)e*DDIM+kl)*HDIM+h0;
            #pragma unroll
            for(int i=0;i<3;i++){
                int ch=tid+128*i;
                if(ch<320){
                    int r=ch/10, c=ch-r*10;
                    cpa16(st+S2_BHI+r*176+c*16, bh+(size_t)r*HDIM+c*8);
                }
            }
        }
        cpcommit();
    };

    const int mw=(w&1)*64, nw=(w>>1)*40;
    float C[4][5][4];
    #pragma unroll
    for(int i=0;i<4;i++)
        #pragma unroll
        for(int j=0;j<5;j++)
            #pragma unroll
            for(int q=0;q<4;q++) C[i][j][q]=0.f;

    const int rl=lane&15;
    const unsigned aswz=((rl>>1)&3);

    LOAD(0); LOAD(1); LOAD(2);
    for(int kc=0;kc<NCH;kc++){
        if(kc==NCH-1) cpwait<0>(); else cpwait<2>();
        __syncthreads();
        LOAD(kc+3);
        const unsigned ab=db+(unsigned)(kc&3)*S2_STAGE;
        #pragma unroll
        for(int ks=0;ks<2;ks++){
            unsigned a[4][4],b_h[5][2];
            const unsigned bbase=ab+S2_BHI+(unsigned)(ks*16+rl)*176;
            #pragma unroll
            for(int p=0;p<2;p++){
                unsigned r4[4];
                ldsm4t(r4, bbase+(unsigned)(nw+(2*p+(lane>>4))*8)*2);
                b_h[2*p][0]=r4[0];   b_h[2*p][1]=r4[1];
                b_h[2*p+1][0]=r4[2]; b_h[2*p+1][1]=r4[3];
            }
            ldsm2t(b_h[4],bbase+(unsigned)(nw+4*8)*2);
            const unsigned aoff=ab+(unsigned)(mw+rl)*64+((((lane>>4)+ks*2)^aswz)*16);
            #pragma unroll
            for(int mt=0;mt<4;mt++) ldsm4(a[mt],aoff+mt*1024);
            #pragma unroll
            for(int mt=0;mt<4;mt++)
                #pragma unroll
                for(int nt=0;nt<5;nt++)
                    mma_fp(C[mt][nt],a[mt],b_h[nt]);
        }
    }

    const int grp=lane>>2, tq=lane&3;
    #pragma unroll
    for(int nt=0;nt<5;nt++){
        const int colL=nw+nt*8+tq*2;
        const int col=h0+colL;
        #pragma unroll
        for(int mt=0;mt<4;mt++)
            #pragma unroll
            for(int h=0;h<2;h++){
                const int row=mw+mt*16+grp+h*8;
                float v0=C[mt][nt][2*h], v1=C[mt][nt][2*h+1];
                #pragma unroll
                for(int e2=0;e2<NEXP;e2++){
                    float r=sRw[row*8+e2];
                    v0=fmaf(r,sBd[e2*80+colL],v0);
                    v1=fmaf(r,sBd[e2*80+colL+1],v1);
                }
                float2 t; t.x=v0; t.y=v1;
                *(float2*)(out+(size_t)(m0+row)*HDIM+col)=t;
            }
    }
}

extern "C" void kernel_launch(void* const* d_in, const int* in_sizes, int n_in,
                              void* d_out, int out_size)
{
    const float* x  =(const float*)d_in[0];
    const float* rw =(const float*)d_in[1];
    const float* wgu=(const float*)d_in[2];
    const float* bgu=(const float*)d_in[3];
    const float* wd =(const float*)d_in[4];
    const float* bd =(const float*)d_in[5];
    float* out=(float*)d_out;

    cudaFuncSetAttribute(gemm1_kernel, cudaFuncAttributeMaxDynamicSharedMemorySize, 4*S1_STAGE);
    cudaFuncSetAttribute(gemm2_kernel, cudaFuncAttributeMaxDynamicSharedMemorySize, 4*S2_STAGE);

    cvt_kernel<<<2368,256>>>((const float4*)x,(const float4*)wgu,(const float4*)wd);
    gemm1_kernel<<<dim3(45,8,NEXP),128,4*S1_STAGE>>>(rw,bgu);
    gemm2_kernel<<<dim3(36,8),128,4*S2_STAGE>>>(rw,bd,out);
}